// round 8
// baseline (speedup 1.0000x reference)
#include <cuda_runtime.h>
#include <cuda_bf16.h>

// Problem constants
#define Bb 2
#define Ss 2048
#define Ee 1024
#define Hh 16
#define Dd 64
#define SCALE (1.0f/32.0f)   // 1/sqrt(E)

typedef __nv_bfloat16 bf;

// ---------------------------------------------------------------------------
// Scratch (device globals; allocation inside kernel_launch is forbidden)
// ---------------------------------------------------------------------------
__device__ bf    g_q  [(size_t)Bb*Hh*Ss*Dd];   // [b,h,s,d]
__device__ bf    g_kT [(size_t)Bb*Hh*Dd*Ss];   // [b,h,d,s] (transposed K)
__device__ bf    g_v  [(size_t)Bb*Hh*Ss*Dd];   // [b,h,s,d]
__device__ float g_sk [(size_t)Bb*Hh*Ss];      // 0.5*SCALE*||k||^2
__device__ float g_att[(size_t)Bb*Ss*Ee];      // attention out, [b,s,e]

// ---------------------------------------------------------------------------
// Helpers
// ---------------------------------------------------------------------------
__device__ __forceinline__ unsigned s2u(const void* p) {
    return (unsigned)__cvta_generic_to_shared(p);
}
__device__ __forceinline__ unsigned f22bf(float x, float y) {
    __nv_bfloat162 h = __floats2bfloat162_rn(x, y);
    return *(unsigned*)&h;
}
__device__ __forceinline__ void mma_bf16(float* c, const unsigned* a, const unsigned* b) {
    asm volatile(
        "mma.sync.aligned.m16n8k16.row.col.f32.bf16.bf16.f32 "
        "{%0,%1,%2,%3}, {%4,%5,%6,%7}, {%8,%9}, {%0,%1,%2,%3};"
        : "+f"(c[0]), "+f"(c[1]), "+f"(c[2]), "+f"(c[3])
        : "r"(a[0]), "r"(a[1]), "r"(a[2]), "r"(a[3]), "r"(b[0]), "r"(b[1]));
}
__device__ __forceinline__ void ldmA(unsigned* a, unsigned saddr) {
    asm volatile("ldmatrix.sync.aligned.m8n8.x4.shared.b16 {%0,%1,%2,%3}, [%4];"
        : "=r"(a[0]), "=r"(a[1]), "=r"(a[2]), "=r"(a[3]) : "r"(saddr));
}
// B fragments for TWO adjacent n8 tiles (n16) in one x4.trans:
// b[0],b[1] = k0-7/k8-15 of n0-7 ; b[2],b[3] = of n8-15.
__device__ __forceinline__ void ldmB4(unsigned* b, unsigned saddr) {
    asm volatile("ldmatrix.sync.aligned.m8n8.x4.trans.shared.b16 {%0,%1,%2,%3}, [%4];"
        : "=r"(b[0]), "=r"(b[1]), "=r"(b[2]), "=r"(b[3]) : "r"(saddr));
}
__device__ __forceinline__ void cp16(unsigned dst, const void* src) {
    asm volatile("cp.async.cg.shared.global [%0], [%1], 16;" :: "r"(dst), "l"(src));
}
#define CP_COMMIT() asm volatile("cp.async.commit_group;")
#define CP_WAIT0()  asm volatile("cp.async.wait_group 0;")

// ---------------------------------------------------------------------------
// Kernel 1: fused QKV projection, bf16 m16n8k16, fp32 accum (legacy mma —
// tcgen05 unavailable under this harness's sm_100 ptxas target).
// Block tile 128x128, K-chunk 32, double-buffered smem + register prefetch.
// ---------------------------------------------------------------------------
__global__ __launch_bounds__(256, 2) void proj_kernel(
    const float* __restrict__ Xq, const float* __restrict__ Xk, const float* __restrict__ Xv,
    const float* __restrict__ Wq, const float* __restrict__ Wk, const float* __restrict__ Wv,
    const float* __restrict__ Bq, const float* __restrict__ Bk, const float* __restrict__ Bv)
{
    const int z = blockIdx.z;
    const float* X    = (z==0) ? Xq : ((z==1) ? Xk : Xv);
    const float* W    = (z==0) ? Wq : ((z==1) ? Wk : Wv);
    const float* bias = (z==0) ? Bq : ((z==1) ? Bk : Bv);

    __shared__ bf Xs[2][128][40];   // [buf][m][k], pad 8
    __shared__ bf Ws[2][32][136];   // [buf][k][n], pad 8

    const int tid  = threadIdx.x;
    const int wid  = tid >> 5, lane = tid & 31;
    const int g    = lane >> 2, qd = lane & 3;
    const int wm   = (wid & 1) * 64;
    const int wn   = (wid >> 1) * 32;
    const int m0   = blockIdx.x * 128;
    const int n0   = blockIdx.y * 128;

    const int arow_l = (lane & 7) + ((lane >> 3) & 1) * 8;
    const int acol_l = (lane >> 4) * 8;
    const int brow_l = (lane & 7) + ((lane >> 3) & 1) * 8;
    const int bcol_l = (lane >> 4) * 8;       // n8 offset for x4.trans upper matrices

    const int xr_r  = tid >> 3,  xr_c = (tid & 7) << 2;     // +u*32 rows
    const int wr_k  = tid >> 5,  wr_c = (tid & 31) << 2;    // +u*8 k-rows
    const int wn_h  = (n0 + wr_c) >> 6, wn_d = (n0 + wr_c) & 63;

    uint2 xr[4], wr[4];
    auto prefetch = [&](int k0) {
        #pragma unroll
        for (int u = 0; u < 4; u++) {
            float4 xv = *(const float4*)(X + (size_t)(m0 + xr_r + u*32) * Ee + k0 + xr_c);
            xr[u] = make_uint2(f22bf(xv.x, xv.y), f22bf(xv.z, xv.w));
            float4 wv = *(const float4*)(W + (size_t)wn_h * (Ee*Dd)
                                           + (size_t)(k0 + wr_k + u*8) * Dd + wn_d);
            wr[u] = make_uint2(f22bf(wv.x, wv.y), f22bf(wv.z, wv.w));
        }
    };

    float acc[4][4][4];
    #pragma unroll
    for (int mi = 0; mi < 4; mi++)
        #pragma unroll
        for (int nj = 0; nj < 4; nj++)
            #pragma unroll
            for (int r = 0; r < 4; r++) acc[mi][nj][r] = 0.f;

    prefetch(0);

    for (int k0 = 0; k0 < Ee; k0 += 32) {
        const int buf = (k0 >> 5) & 1;
        #pragma unroll
        for (int u = 0; u < 4; u++) {
            *(uint2*)&Xs[buf][xr_r + u*32][xr_c] = xr[u];
            *(uint2*)&Ws[buf][wr_k + u*8][wr_c] = wr[u];
        }
        __syncthreads();
        if (k0 + 32 < Ee) prefetch(k0 + 32);   // overlapped with mma below

        #pragma unroll
        for (int ks = 0; ks < 2; ks++) {
            unsigned a[4][4], b[2][4];
            #pragma unroll
            for (int mi = 0; mi < 4; mi++)
                ldmA(a[mi], s2u(&Xs[buf][wm + mi*16 + arow_l][ks*16 + acol_l]));
            #pragma unroll
            for (int p = 0; p < 2; p++)
                ldmB4(b[p], s2u(&Ws[buf][ks*16 + brow_l][wn + p*16 + bcol_l]));
            #pragma unroll
            for (int mi = 0; mi < 4; mi++)
                #pragma unroll
                for (int p = 0; p < 2; p++) {
                    mma_bf16(acc[mi][2*p    ], a[mi], &b[p][0]);
                    mma_bf16(acc[mi][2*p + 1], a[mi], &b[p][2]);
                }
        }
        // no trailing sync: next iter writes the other buffer
    }

    // Epilogue: +bias, convert to bf16
    #pragma unroll
    for (int mi = 0; mi < 4; mi++) {
        #pragma unroll
        for (int half = 0; half < 2; half++) {
            int m = m0 + wm + mi*16 + g + half*8;
            int bb = m >> 11, s = m & 2047;
            #pragma unroll
            for (int nj = 0; nj < 4; nj++) {
                int n = n0 + wn + nj*8 + 2*qd;
                int h = n >> 6, d = n & 63;
                float v0 = acc[mi][nj][half*2 + 0] + bias[h*Dd + d];
                float v1 = acc[mi][nj][half*2 + 1] + bias[h*Dd + d + 1];
                size_t bh = (size_t)bb * Hh + h;
                if (z == 1) {
                    g_kT[(bh*Dd + d    )*Ss + s] = __float2bfloat16_rn(v0);
                    g_kT[(bh*Dd + d + 1)*Ss + s] = __float2bfloat16_rn(v1);
                } else {
                    bf* out = (z == 0) ? g_q : g_v;
                    *(unsigned*)&out[(bh*Ss + s)*Dd + d] = f22bf(v0, v1);
                }
            }
        }
    }
}

// ---------------------------------------------------------------------------
// Kernel 2: g_sk = 0.5*SCALE*||k||^2 from the SAME bf16 k the mma consumes.
// ---------------------------------------------------------------------------
__global__ __launch_bounds__(256) void knorm_kernel()
{
    int idx = blockIdx.x * 256 + threadIdx.x;
    int bh = idx >> 11;
    int s  = idx & 2047;
    const bf* kp = g_kT + (size_t)bh * Dd * Ss + s;
    float acc = 0.f;
    #pragma unroll
    for (int d = 0; d < Dd; d++) {
        float v = __bfloat162float(kp[(size_t)d * Ss]);
        acc = fmaf(v, v, acc);
    }
    g_sk[idx] = 0.5f * SCALE * acc;
}

// ---------------------------------------------------------------------------
// Kernel 3: flash attention, bf16 m16n8k16, fixed-max softmax (scores <= 0).
// BQ=128 q-rows/block, 8 warps (16 rows each): K/V smem + L2 traffic HALVED
// vs BQ=64.  Q staged across the contiguous Ks[0]|Ks[1] region (exactly 18432B),
// A-frags hoisted to regs; P register reuse; cp.async double buffer; ldmB4.
// ---------------------------------------------------------------------------
__global__ __launch_bounds__(256) void flash_kernel()
{
    __shared__ __align__(16) unsigned char smbuf[45056];
    bf* Ks[2] = { (bf*)smbuf,            (bf*)(smbuf +  9216) };   // [64][72] each
    bf* Vs[2] = { (bf*)(smbuf + 18432),  (bf*)(smbuf + 27648) };   // [64][72] each
    float* sks = (float*)(smbuf + 36864);                          // [2048]

    const int bh = blockIdx.y;
    const int q0 = blockIdx.x * 128;
    const int tid = threadIdx.x;
    const int wid = tid >> 5, lane = tid & 31;
    const int g = lane >> 2, qd = lane & 3;

    const bf* Qg   = g_q  + ((size_t)bh * Ss + q0) * Dd;
    const bf* KTg  = g_kT + (size_t)bh * Dd * Ss;
    const bf* Vg   = g_v  + (size_t)bh * Ss * Dd;
    const float* skg = g_sk + (size_t)bh * Ss;

    const int arow_l = (lane & 7) + ((lane >> 3) & 1) * 8;
    const int acol_l = (lane >> 4) * 8;
    const int brow_l = (lane & 7) + ((lane >> 3) & 1) * 8;
    const int bcol_l = (lane >> 4) * 8;
    const int wrow = wid * 16;          // 0..112
    const int crow = wrow + g;

    const int ld_r  = tid >> 3;         // 0..31
    const int ld_c8 = (tid & 7) << 3;

    // ---- Prologue: Q [128][64] -> staging (Ks[0]|Ks[1], pitch 72) -> A regs ----
    {
        bf* Qst = Ks[0];   // 128*72*2 = 18432 B = Ks[0]+Ks[1] exactly
        #pragma unroll
        for (int u = 0; u < 4; u++)
            *(uint4*)&Qst[(ld_r + u*32)*72 + ld_c8] =
                *(const uint4*)(Qg + (size_t)(ld_r + u*32) * Dd + ld_c8);
        #pragma unroll
        for (int u = 0; u < 2; u++) {
            int idx = u * 256 + tid;
            *(float4*)&sks[idx*4] = *(const float4*)(skg + idx*4);
        }
        __syncthreads();
    }
    unsigned qa[4][4];
    #pragma unroll
    for (int t = 0; t < 4; t++)
        ldmA(qa[t], s2u(&Ks[0][(wrow + arow_l)*72 + t*16 + acol_l]));

    // row constants: 0.5*SCALE*||q||^2 for rows crow and crow+8
    float sq0 = 0.f, sq1 = 0.f;
    {
        const bf* r0 = &Ks[0][crow*72];
        const bf* r1 = &Ks[0][(crow+8)*72];
        #pragma unroll
        for (int d = 0; d < Dd; d++) {
            float v0 = __bfloat162float(r0[d]);
            float v1 = __bfloat162float(r1[d]);
            sq0 = fmaf(v0, v0, sq0);
            sq1 = fmaf(v1, v1, sq1);
        }
        sq0 *= 0.5f * SCALE;
        sq1 *= 0.5f * SCALE;
    }
    __syncthreads();   // Q staging dead; cp.async may overwrite

    auto issue_loads = [&](int buf, int k0) {
        #pragma unroll
        for (int u = 0; u < 2; u++) {
            int r = ld_r + u*32;
            cp16(s2u(&Ks[buf][r*72 + ld_c8]), KTg + (size_t)r * Ss + k0 + ld_c8);
            cp16(s2u(&Vs[buf][r*72 + ld_c8]), Vg  + (size_t)(k0 + r) * Dd + ld_c8);
        }
        CP_COMMIT();
    };
    issue_loads(0, 0);

    float l0 = 0.f, l1 = 0.f;
    float oacc[8][4];
    #pragma unroll
    for (int j = 0; j < 8; j++)
        #pragma unroll
        for (int r = 0; r < 4; r++) oacc[j][r] = 0.f;

    for (int it = 0; it < Ss/64; it++) {
        const int k0 = it * 64;
        const int buf = it & 1;
        CP_WAIT0();
        __syncthreads();
        if (it + 1 < Ss/64) issue_loads(buf ^ 1, k0 + 64);

        // ---- scores: Q(reg) x K^T[d][key], ldmB4 covers n16 per load ----
        float sc[8][4];
        #pragma unroll
        for (int j = 0; j < 8; j++)
            #pragma unroll
            for (int r = 0; r < 4; r++) sc[j][r] = 0.f;

        #pragma unroll
        for (int t = 0; t < 4; t++) {
            #pragma unroll
            for (int p = 0; p < 4; p++) {
                unsigned b[4];
                ldmB4(b, s2u(&Ks[buf][(t*16 + brow_l)*72 + p*16 + bcol_l]));
                mma_bf16(sc[2*p    ], qa[t], &b[0]);
                mma_bf16(sc[2*p + 1], qa[t], &b[2]);
            }
        }

        // ---- exact softmax, fixed max 0: p = exp(qk*SCALE - sk - sq) ----
        #pragma unroll
        for (int j = 0; j < 8; j++) {
            #pragma unroll
            for (int c = 0; c < 2; c++) {
                float skc = sks[k0 + j*8 + 2*qd + c];
                float p0 = __expf(fmaf(sc[j][c],   SCALE, -skc) - sq0);
                float p1 = __expf(fmaf(sc[j][2+c], SCALE, -skc) - sq1);
                sc[j][c]   = p0; l0 += p0;
                sc[j][2+c] = p1; l1 += p1;
            }
        }

        // ---- PV: P straight from registers (C-frag == A-frag layout) ----
        #pragma unroll
        for (int t = 0; t < 4; t++) {
            unsigned a[4];
            a[0] = f22bf(sc[2*t  ][0], sc[2*t  ][1]);
            a[1] = f22bf(sc[2*t  ][2], sc[2*t  ][3]);
            a[2] = f22bf(sc[2*t+1][0], sc[2*t+1][1]);
            a[3] = f22bf(sc[2*t+1][2], sc[2*t+1][3]);
            #pragma unroll
            for (int p = 0; p < 4; p++) {
                unsigned b[4];
                ldmB4(b, s2u(&Vs[buf][(t*16 + brow_l)*72 + p*16 + bcol_l]));
                mma_bf16(oacc[2*p    ], a, &b[0]);
                mma_bf16(oacc[2*p + 1], a, &b[2]);
            }
        }
    }

    // reduce l across the 4 qd lanes once
    l0 += __shfl_xor_sync(0xffffffffu, l0, 1);
    l0 += __shfl_xor_sync(0xffffffffu, l0, 2);
    l1 += __shfl_xor_sync(0xffffffffu, l1, 1);
    l1 += __shfl_xor_sync(0xffffffffu, l1, 2);

    // Epilogue: normalize, write fp32 concat layout g_att[b, s, h*64 + dv]
    const int b = bh >> 4, h = bh & 15;
    const int s0 = q0 + crow, s1 = s0 + 8;
    float inv0 = 1.0f / l0, inv1 = 1.0f / l1;
    #pragma unroll
    for (int j = 0; j < 8; j++) {
        int col = h*Dd + j*8 + 2*qd;
        *(float2*)&g_att[((size_t)b*Ss + s0)*Ee + col] =
            make_float2(oacc[j][0]*inv0, oacc[j][1]*inv0);
        *(float2*)&g_att[((size_t)b*Ss + s1)*Ee + col] =
            make_float2(oacc[j][2]*inv1, oacc[j][3]*inv1);
    }
}

// ---------------------------------------------------------------------------
// Kernel 4: residual add + custom LayerNorm (ddof=1, shift in divisor).
// ---------------------------------------------------------------------------
__global__ __launch_bounds__(256) void ln_kernel(
    const float* __restrict__ resid, const float* __restrict__ gamma,
    const float* __restrict__ beta, float* __restrict__ out)
{
    const int row = blockIdx.x;            // 0..4095
    const float* xa = g_att + (size_t)row * Ee;
    const float* xr = resid + (size_t)row * Ee;
    const int tid = threadIdx.x;

    float4 a = *(const float4*)(xa + tid*4);
    float4 r = *(const float4*)(xr + tid*4);
    float x0 = a.x + r.x, x1 = a.y + r.y, x2 = a.z + r.z, x3 = a.w + r.w;

    float sum = x0 + x1 + x2 + x3;
    float sq  = x0*x0 + x1*x1 + x2*x2 + x3*x3;
    #pragma unroll
    for (int o = 16; o >= 1; o >>= 1) {
        sum += __shfl_xor_sync(0xffffffffu, sum, o);
        sq  += __shfl_xor_sync(0xffffffffu, sq,  o);
    }
    __shared__ float rs[8], rq[8];
    int w = tid >> 5, lane = tid & 31;
    if (lane == 0) { rs[w] = sum; rq[w] = sq; }
    __syncthreads();
    float ts = 0.f, tq = 0.f;
    #pragma unroll
    for (int i = 0; i < 8; i++) { ts += rs[i]; tq += rq[i]; }

    float mean = ts * (1.0f/1024.0f);
    float var  = (tq - 1024.0f * mean * mean) * (1.0f/1023.0f);  // ddof=1
    float stdv = sqrtf(var);

    float4 gv = *(const float4*)(gamma + tid*4);
    float4 bv = *(const float4*)(beta  + tid*4);
    float4 o4;
    o4.x = gv.x * (x0 - mean) / (stdv + 1e-6f + bv.x);
    o4.y = gv.y * (x1 - mean) / (stdv + 1e-6f + bv.y);
    o4.z = gv.z * (x2 - mean) / (stdv + 1e-6f + bv.z);
    o4.w = gv.w * (x3 - mean) / (stdv + 1e-6f + bv.w);
    *(float4*)(out + (size_t)row * Ee + tid*4) = o4;
}

// ---------------------------------------------------------------------------
// Launch.
// ---------------------------------------------------------------------------
extern "C" void kernel_launch(void* const* d_in, const int* in_sizes, int n_in,
                              void* d_out, int out_size)
{
    (void)in_sizes; (void)n_in; (void)out_size;
    const float* query = (const float*)d_in[0];
    const float* key   = (const float*)d_in[1];
    const float* value = (const float*)d_in[2];
    const float* resid = (const float*)d_in[3];
    const float* Wq = (const float*)d_in[4];
    const float* bq = (const float*)d_in[5];
    const float* Wk = (const float*)d_in[6];
    const float* bk = (const float*)d_in[7];
    const float* Wv = (const float*)d_in[8];
    const float* bv = (const float*)d_in[9];
    const float* gamma = (const float*)d_in[10];
    const float* beta  = (const float*)d_in[11];
    float* out = (float*)d_out;

    dim3 gproj(32, 8, 3);
    proj_kernel<<<gproj, 256>>>(query, key, value, Wq, Wk, Wv, bq, bk, bv);
    knorm_kernel<<<256, 256>>>();
    flash_kernel<<<dim3(16, 32), 256>>>();   // BQ=128
    ln_kernel<<<4096, 256>>>(resid, gamma, beta, out);
}

// round 9
// speedup vs baseline: 1.0256x; 1.0256x over previous
#include <cuda_runtime.h>
#include <cuda_bf16.h>

// Problem constants
#define Bb 2
#define Ss 2048
#define Ee 1024
#define Hh 16
#define Dd 64
#define SCALE (1.0f/32.0f)   // 1/sqrt(E)
#define NSPLIT 2             // flash key-splits

typedef __nv_bfloat16 bf;

// ---------------------------------------------------------------------------
// Scratch (device globals; allocation inside kernel_launch is forbidden)
// ---------------------------------------------------------------------------
__device__ bf    g_q  [(size_t)Bb*Hh*Ss*Dd];   // [b,h,s,d]
__device__ bf    g_kT [(size_t)Bb*Hh*Dd*Ss];   // [b,h,d,s] (transposed K)
__device__ bf    g_v  [(size_t)Bb*Hh*Ss*Dd];   // [b,h,s,d]
__device__ float g_sk [(size_t)Bb*Hh*Ss];      // 0.5*SCALE*||k||^2
__device__ float g_po [(size_t)NSPLIT*Bb*Hh*Ss*Dd];  // unnormalized partial out
__device__ float g_l  [(size_t)NSPLIT*Bb*Hh*Ss];     // partial softmax denominators

// ---------------------------------------------------------------------------
// Helpers
// ---------------------------------------------------------------------------
__device__ __forceinline__ unsigned s2u(const void* p) {
    return (unsigned)__cvta_generic_to_shared(p);
}
__device__ __forceinline__ unsigned f22bf(float x, float y) {
    __nv_bfloat162 h = __floats2bfloat162_rn(x, y);
    return *(unsigned*)&h;
}
__device__ __forceinline__ void mma_bf16(float* c, const unsigned* a, const unsigned* b) {
    asm volatile(
        "mma.sync.aligned.m16n8k16.row.col.f32.bf16.bf16.f32 "
        "{%0,%1,%2,%3}, {%4,%5,%6,%7}, {%8,%9}, {%0,%1,%2,%3};"
        : "+f"(c[0]), "+f"(c[1]), "+f"(c[2]), "+f"(c[3])
        : "r"(a[0]), "r"(a[1]), "r"(a[2]), "r"(a[3]), "r"(b[0]), "r"(b[1]));
}
__device__ __forceinline__ void ldmA(unsigned* a, unsigned saddr) {
    asm volatile("ldmatrix.sync.aligned.m8n8.x4.shared.b16 {%0,%1,%2,%3}, [%4];"
        : "=r"(a[0]), "=r"(a[1]), "=r"(a[2]), "=r"(a[3]) : "r"(saddr));
}
// B fragments for TWO adjacent n8 tiles (n16) in one x4.trans
__device__ __forceinline__ void ldmB4(unsigned* b, unsigned saddr) {
    asm volatile("ldmatrix.sync.aligned.m8n8.x4.trans.shared.b16 {%0,%1,%2,%3}, [%4];"
        : "=r"(b[0]), "=r"(b[1]), "=r"(b[2]), "=r"(b[3]) : "r"(saddr));
}
__device__ __forceinline__ void cp16(unsigned dst, const void* src) {
    asm volatile("cp.async.cg.shared.global [%0], [%1], 16;" :: "r"(dst), "l"(src));
}
#define CP_COMMIT() asm volatile("cp.async.commit_group;")
#define CP_WAIT0()  asm volatile("cp.async.wait_group 0;")

// ---------------------------------------------------------------------------
// Kernel 1: fused QKV projection, bf16 m16n8k16, fp32 accum (legacy mma —
// tcgen05 unavailable under this harness's sm_100 ptxas target).
// Block tile 128x128, K-chunk 32, double-buffered smem + register prefetch.
// ---------------------------------------------------------------------------
__global__ __launch_bounds__(256, 2) void proj_kernel(
    const float* __restrict__ Xq, const float* __restrict__ Xk, const float* __restrict__ Xv,
    const float* __restrict__ Wq, const float* __restrict__ Wk, const float* __restrict__ Wv,
    const float* __restrict__ Bq, const float* __restrict__ Bk, const float* __restrict__ Bv)
{
    const int z = blockIdx.z;
    const float* X    = (z==0) ? Xq : ((z==1) ? Xk : Xv);
    const float* W    = (z==0) ? Wq : ((z==1) ? Wk : Wv);
    const float* bias = (z==0) ? Bq : ((z==1) ? Bk : Bv);

    __shared__ bf Xs[2][128][40];   // [buf][m][k], pad 8
    __shared__ bf Ws[2][32][136];   // [buf][k][n], pad 8

    const int tid  = threadIdx.x;
    const int wid  = tid >> 5, lane = tid & 31;
    const int g    = lane >> 2, qd = lane & 3;
    const int wm   = (wid & 1) * 64;
    const int wn   = (wid >> 1) * 32;
    const int m0   = blockIdx.x * 128;
    const int n0   = blockIdx.y * 128;

    const int arow_l = (lane & 7) + ((lane >> 3) & 1) * 8;
    const int acol_l = (lane >> 4) * 8;
    const int brow_l = (lane & 7) + ((lane >> 3) & 1) * 8;
    const int bcol_l = (lane >> 4) * 8;

    const int xr_r  = tid >> 3,  xr_c = (tid & 7) << 2;     // +u*32 rows
    const int wr_k  = tid >> 5,  wr_c = (tid & 31) << 2;    // +u*8 k-rows
    const int wn_h  = (n0 + wr_c) >> 6, wn_d = (n0 + wr_c) & 63;

    uint2 xr[4], wr[4];
    auto prefetch = [&](int k0) {
        #pragma unroll
        for (int u = 0; u < 4; u++) {
            float4 xv = *(const float4*)(X + (size_t)(m0 + xr_r + u*32) * Ee + k0 + xr_c);
            xr[u] = make_uint2(f22bf(xv.x, xv.y), f22bf(xv.z, xv.w));
            float4 wv = *(const float4*)(W + (size_t)wn_h * (Ee*Dd)
                                           + (size_t)(k0 + wr_k + u*8) * Dd + wn_d);
            wr[u] = make_uint2(f22bf(wv.x, wv.y), f22bf(wv.z, wv.w));
        }
    };

    float acc[4][4][4];
    #pragma unroll
    for (int mi = 0; mi < 4; mi++)
        #pragma unroll
        for (int nj = 0; nj < 4; nj++)
            #pragma unroll
            for (int r = 0; r < 4; r++) acc[mi][nj][r] = 0.f;

    prefetch(0);

    for (int k0 = 0; k0 < Ee; k0 += 32) {
        const int buf = (k0 >> 5) & 1;
        #pragma unroll
        for (int u = 0; u < 4; u++) {
            *(uint2*)&Xs[buf][xr_r + u*32][xr_c] = xr[u];
            *(uint2*)&Ws[buf][wr_k + u*8][wr_c] = wr[u];
        }
        __syncthreads();
        if (k0 + 32 < Ee) prefetch(k0 + 32);   // overlapped with mma below

        #pragma unroll
        for (int ks = 0; ks < 2; ks++) {
            unsigned a[4][4], b[2][4];
            #pragma unroll
            for (int mi = 0; mi < 4; mi++)
                ldmA(a[mi], s2u(&Xs[buf][wm + mi*16 + arow_l][ks*16 + acol_l]));
            #pragma unroll
            for (int p = 0; p < 2; p++)
                ldmB4(b[p], s2u(&Ws[buf][ks*16 + brow_l][wn + p*16 + bcol_l]));
            #pragma unroll
            for (int mi = 0; mi < 4; mi++)
                #pragma unroll
                for (int p = 0; p < 2; p++) {
                    mma_bf16(acc[mi][2*p    ], a[mi], &b[p][0]);
                    mma_bf16(acc[mi][2*p + 1], a[mi], &b[p][2]);
                }
        }
    }

    // Epilogue: +bias, convert to bf16
    #pragma unroll
    for (int mi = 0; mi < 4; mi++) {
        #pragma unroll
        for (int half = 0; half < 2; half++) {
            int m = m0 + wm + mi*16 + g + half*8;
            int bb = m >> 11, s = m & 2047;
            #pragma unroll
            for (int nj = 0; nj < 4; nj++) {
                int n = n0 + wn + nj*8 + 2*qd;
                int h = n >> 6, d = n & 63;
                float v0 = acc[mi][nj][half*2 + 0] + bias[h*Dd + d];
                float v1 = acc[mi][nj][half*2 + 1] + bias[h*Dd + d + 1];
                size_t bh = (size_t)bb * Hh + h;
                if (z == 1) {
                    g_kT[(bh*Dd + d    )*Ss + s] = __float2bfloat16_rn(v0);
                    g_kT[(bh*Dd + d + 1)*Ss + s] = __float2bfloat16_rn(v1);
                } else {
                    bf* out = (z == 0) ? g_q : g_v;
                    *(unsigned*)&out[(bh*Ss + s)*Dd + d] = f22bf(v0, v1);
                }
            }
        }
    }
}

// ---------------------------------------------------------------------------
// Kernel 2: g_sk = 0.5*SCALE*||k||^2 from the SAME bf16 k the mma consumes.
// ---------------------------------------------------------------------------
__global__ __launch_bounds__(256) void knorm_kernel()
{
    int idx = blockIdx.x * 256 + threadIdx.x;
    int bh = idx >> 11;
    int s  = idx & 2047;
    const bf* kp = g_kT + (size_t)bh * Dd * Ss + s;
    float acc = 0.f;
    #pragma unroll
    for (int d = 0; d < Dd; d++) {
        float v = __bfloat162float(kp[(size_t)d * Ss]);
        acc = fmaf(v, v, acc);
    }
    g_sk[idx] = 0.5f * SCALE * acc;
}

// ---------------------------------------------------------------------------
// Kernel 3: flash attention, bf16 m16n8k16, fixed-max softmax, SPLIT-K (2).
// BQ=64, 4 warps; each block covers 1024 keys (16 tiles).  Writes UNNORMALIZED
// partial output + partial l; combine happens in ln_kernel.  The finer work
// quantum cuts block-quantization waste (2048 items over ~740 slots).
// ---------------------------------------------------------------------------
__global__ __launch_bounds__(128) void flash_kernel()
{
    __shared__ __align__(16) unsigned char smbuf[40960];
    bf* Ks[2] = { (bf*)smbuf,            (bf*)(smbuf +  9216) };   // [64][72]
    bf* Vs[2] = { (bf*)(smbuf + 18432),  (bf*)(smbuf + 27648) };   // [64][72]
    float* sks = (float*)(smbuf + 36864);                          // [1024]

    const int bh = blockIdx.y;
    const int q0 = blockIdx.x * 64;
    const int ksp = blockIdx.z;               // 0..NSPLIT-1
    const int kbase = ksp * (Ss / NSPLIT);    // 0 or 1024
    const int tid = threadIdx.x;
    const int wid = tid >> 5, lane = tid & 31;
    const int g = lane >> 2, qd = lane & 3;

    const bf* Qg   = g_q  + ((size_t)bh * Ss + q0) * Dd;
    const bf* KTg  = g_kT + (size_t)bh * Dd * Ss;
    const bf* Vg   = g_v  + (size_t)bh * Ss * Dd;
    const float* skg = g_sk + (size_t)bh * Ss + kbase;

    const int arow_l = (lane & 7) + ((lane >> 3) & 1) * 8;
    const int acol_l = (lane >> 4) * 8;
    const int brow_l = (lane & 7) + ((lane >> 3) & 1) * 8;
    const int bcol_l = (lane >> 4) * 8;
    const int wrow = wid * 16;
    const int crow = wrow + g;

    const int ld_r  = tid >> 3;
    const int ld_c8 = (tid & 7) << 3;

    // ---- Prologue: Q -> staging (Ks[0]) -> A regs; this split's sk row ----
    {
        bf* Qst = Ks[0];
        #pragma unroll
        for (int u = 0; u < 4; u++)
            *(uint4*)&Qst[(ld_r + u*16)*72 + ld_c8] =
                *(const uint4*)(Qg + (size_t)(ld_r + u*16) * Dd + ld_c8);
        #pragma unroll
        for (int u = 0; u < 2; u++) {
            int idx = u * 128 + tid;
            *(float4*)&sks[idx*4] = *(const float4*)(skg + idx*4);
        }
        __syncthreads();
    }
    unsigned qa[4][4];
    #pragma unroll
    for (int t = 0; t < 4; t++)
        ldmA(qa[t], s2u(&Ks[0][(wrow + arow_l)*72 + t*16 + acol_l]));

    // row constants: 0.5*SCALE*||q||^2 for rows crow and crow+8
    float sq0 = 0.f, sq1 = 0.f;
    {
        const bf* r0 = &Ks[0][crow*72];
        const bf* r1 = &Ks[0][(crow+8)*72];
        #pragma unroll
        for (int d = 0; d < Dd; d++) {
            float v0 = __bfloat162float(r0[d]);
            float v1 = __bfloat162float(r1[d]);
            sq0 = fmaf(v0, v0, sq0);
            sq1 = fmaf(v1, v1, sq1);
        }
        sq0 *= 0.5f * SCALE;
        sq1 *= 0.5f * SCALE;
    }
    __syncthreads();   // Q staging dead; cp.async may overwrite

    auto issue_loads = [&](int buf, int k0) {
        #pragma unroll
        for (int u = 0; u < 4; u++) {
            int r = ld_r + u*16;
            cp16(s2u(&Ks[buf][r*72 + ld_c8]), KTg + (size_t)r * Ss + k0 + ld_c8);
            cp16(s2u(&Vs[buf][r*72 + ld_c8]), Vg  + (size_t)(k0 + r) * Dd + ld_c8);
        }
        CP_COMMIT();
    };
    issue_loads(0, kbase);

    float l0 = 0.f, l1 = 0.f;
    float oacc[8][4];
    #pragma unroll
    for (int j = 0; j < 8; j++)
        #pragma unroll
        for (int r = 0; r < 4; r++) oacc[j][r] = 0.f;

    const int NIT = (Ss / NSPLIT) / 64;   // 16
    for (int it = 0; it < NIT; it++) {
        const int k0 = kbase + it * 64;
        const int buf = it & 1;
        CP_WAIT0();
        __syncthreads();
        if (it + 1 < NIT) issue_loads(buf ^ 1, k0 + 64);

        // ---- scores: Q(reg) x K^T[d][key] ----
        float sc[8][4];
        #pragma unroll
        for (int j = 0; j < 8; j++)
            #pragma unroll
            for (int r = 0; r < 4; r++) sc[j][r] = 0.f;

        #pragma unroll
        for (int t = 0; t < 4; t++) {
            #pragma unroll
            for (int p = 0; p < 4; p++) {
                unsigned b[4];
                ldmB4(b, s2u(&Ks[buf][(t*16 + brow_l)*72 + p*16 + bcol_l]));
                mma_bf16(sc[2*p    ], qa[t], &b[0]);
                mma_bf16(sc[2*p + 1], qa[t], &b[2]);
            }
        }

        // ---- exact softmax, fixed max 0: p = exp(qk*SCALE - sk - sq) ----
        #pragma unroll
        for (int j = 0; j < 8; j++) {
            #pragma unroll
            for (int c = 0; c < 2; c++) {
                float skc = sks[it*64 + j*8 + 2*qd + c];
                float p0 = __expf(fmaf(sc[j][c],   SCALE, -skc) - sq0);
                float p1 = __expf(fmaf(sc[j][2+c], SCALE, -skc) - sq1);
                sc[j][c]   = p0; l0 += p0;
                sc[j][2+c] = p1; l1 += p1;
            }
        }

        // ---- PV: P straight from registers (C-frag == A-frag layout) ----
        #pragma unroll
        for (int t = 0; t < 4; t++) {
            unsigned a[4];
            a[0] = f22bf(sc[2*t  ][0], sc[2*t  ][1]);
            a[1] = f22bf(sc[2*t  ][2], sc[2*t  ][3]);
            a[2] = f22bf(sc[2*t+1][0], sc[2*t+1][1]);
            a[3] = f22bf(sc[2*t+1][2], sc[2*t+1][3]);
            #pragma unroll
            for (int p = 0; p < 4; p++) {
                unsigned b[4];
                ldmB4(b, s2u(&Vs[buf][(t*16 + brow_l)*72 + p*16 + bcol_l]));
                mma_bf16(oacc[2*p    ], a, &b[0]);
                mma_bf16(oacc[2*p + 1], a, &b[2]);
            }
        }
    }

    // reduce l across the 4 qd lanes once
    l0 += __shfl_xor_sync(0xffffffffu, l0, 1);
    l0 += __shfl_xor_sync(0xffffffffu, l0, 2);
    l1 += __shfl_xor_sync(0xffffffffu, l1, 1);
    l1 += __shfl_xor_sync(0xffffffffu, l1, 2);

    // Epilogue: UNNORMALIZED partial out + l (combine happens in ln_kernel)
    const int s0 = q0 + crow, s1 = s0 + 8;
    float* po = g_po + ((size_t)ksp * (Bb*Hh) + bh) * (Ss * Dd);
    #pragma unroll
    for (int j = 0; j < 8; j++) {
        int col = j*8 + 2*qd;
        *(float2*)&po[(size_t)s0 * Dd + col] = make_float2(oacc[j][0], oacc[j][1]);
        *(float2*)&po[(size_t)s1 * Dd + col] = make_float2(oacc[j][2], oacc[j][3]);
    }
    if (qd == 0) {
        float* pl = g_l + ((size_t)ksp * (Bb*Hh) + bh) * Ss;
        pl[s0] = l0;
        pl[s1] = l1;
    }
}

// ---------------------------------------------------------------------------
// Kernel 4: split-combine + residual add + custom LayerNorm.
// x = (po0+po1)/(l0+l1) + resid;  out = scale*(x-mean)/(std_ddof1+eps+shift)
// ---------------------------------------------------------------------------
__global__ __launch_bounds__(256) void ln_kernel(
    const float* __restrict__ resid, const float* __restrict__ gamma,
    const float* __restrict__ beta, float* __restrict__ out)
{
    const int row = blockIdx.x;            // 0..4095 = b*2048 + s
    const int b = row >> 11, s = row & 2047;
    const int tid = threadIdx.x;
    const int h = tid >> 4;                // head for this thread's 4 cols
    const int dv4 = (tid & 15) << 2;
    const size_t bh = (size_t)b * Hh + h;

    const float* po0 = g_po + (bh           ) * (Ss * Dd) + (size_t)s * Dd + dv4;
    const float* po1 = g_po + ((size_t)Bb*Hh + bh) * (Ss * Dd) + (size_t)s * Dd + dv4;
    float linv = 1.0f / (g_l[bh * Ss + s] + g_l[((size_t)Bb*Hh + bh) * Ss + s]);

    float4 a0 = *(const float4*)po0;
    float4 a1 = *(const float4*)po1;
    float4 r  = *(const float4*)(resid + (size_t)row * Ee + tid*4);
    float x0 = (a0.x + a1.x) * linv + r.x;
    float x1 = (a0.y + a1.y) * linv + r.y;
    float x2 = (a0.z + a1.z) * linv + r.z;
    float x3 = (a0.w + a1.w) * linv + r.w;

    float sum = x0 + x1 + x2 + x3;
    float sq  = x0*x0 + x1*x1 + x2*x2 + x3*x3;
    #pragma unroll
    for (int o = 16; o >= 1; o >>= 1) {
        sum += __shfl_xor_sync(0xffffffffu, sum, o);
        sq  += __shfl_xor_sync(0xffffffffu, sq,  o);
    }
    __shared__ float rs[8], rq[8];
    int w = tid >> 5, lane = tid & 31;
    if (lane == 0) { rs[w] = sum; rq[w] = sq; }
    __syncthreads();
    float ts = 0.f, tq = 0.f;
    #pragma unroll
    for (int i = 0; i < 8; i++) { ts += rs[i]; tq += rq[i]; }

    float mean = ts * (1.0f/1024.0f);
    float var  = (tq - 1024.0f * mean * mean) * (1.0f/1023.0f);  // ddof=1
    float stdv = sqrtf(var);

    float4 gv = *(const float4*)(gamma + tid*4);
    float4 bv = *(const float4*)(beta  + tid*4);
    float4 o4;
    o4.x = gv.x * (x0 - mean) / (stdv + 1e-6f + bv.x);
    o4.y = gv.y * (x1 - mean) / (stdv + 1e-6f + bv.y);
    o4.z = gv.z * (x2 - mean) / (stdv + 1e-6f + bv.z);
    o4.w = gv.w * (x3 - mean) / (stdv + 1e-6f + bv.w);
    *(float4*)(out + (size_t)row * Ee + tid*4) = o4;
}

// ---------------------------------------------------------------------------
// Launch.
// ---------------------------------------------------------------------------
extern "C" void kernel_launch(void* const* d_in, const int* in_sizes, int n_in,
                              void* d_out, int out_size)
{
    (void)in_sizes; (void)n_in; (void)out_size;
    const float* query = (const float*)d_in[0];
    const float* key   = (const float*)d_in[1];
    const float* value = (const float*)d_in[2];
    const float* resid = (const float*)d_in[3];
    const float* Wq = (const float*)d_in[4];
    const float* bq = (const float*)d_in[5];
    const float* Wk = (const float*)d_in[6];
    const float* bk = (const float*)d_in[7];
    const float* Wv = (const float*)d_in[8];
    const float* bv = (const float*)d_in[9];
    const float* gamma = (const float*)d_in[10];
    const float* beta  = (const float*)d_in[11];
    float* out = (float*)d_out;

    dim3 gproj(32, 8, 3);
    proj_kernel<<<gproj, 256>>>(query, key, value, Wq, Wk, Wv, bq, bk, bv);
    knorm_kernel<<<256, 256>>>();
    flash_kernel<<<dim3(32, 32, NSPLIT), 128>>>();
    ln_kernel<<<4096, 256>>>(resid, gamma, beta, out);
}